// round 6
// baseline (speedup 1.0000x reference)
#include <cuda_runtime.h>
#include <cuda_fp16.h>

// PatternDetector: B=131072 rows x L=256 int32 in [0,40). Output Bx4 f32.
//
// Stable "nonzeros-first" argsort preserves order -> all features are
// functions of consecutive-nonzero pairs -> single forward scan per row.
// dec = (n-1) - rep - inc.
//
// R6: four 16-element chains per thread packed into TWO independent half2
// recurrences (X={C0,C2}, Y={C1,C3}). Values v<40 carried as half 1024+v
// (bits 0x6400|v, exact). Compares via __heq2/__hgt2/__hne2, prev updates
// via exact __hfma2 blends. Chain inits for C1/C2/C3 come from register
// words (last 4 elements before each boundary; >=2 nonzeros w.p. 1-6e-5,
// rare smem fallback). Sentinel 127 -> 1151.0 kills all guards.

constexpr int TPB     = 256;
constexpr int RPB     = 64;
constexpr int L_LEN   = 256;
constexpr int CSTRIDE = 80;    // 64B chunk in 20-word slot: LDS.128 conflict-free

__device__ __forceinline__ __half2 h2bits(unsigned u) {
    return *reinterpret_cast<__half2*>(&u);
}
__device__ __forceinline__ unsigned bitsh2(__half2 h) {
    return *reinterpret_cast<unsigned*>(&h);
}

// branchless "last two nonzeros" of a 4-byte word (ascending position order)
__device__ __forceinline__ void last2nz_word(unsigned w, int& p1, int& p2, int& cnt)
{
    p1 = 0; p2 = 0; cnt = 0;
    #pragma unroll
    for (int k = 0; k < 4; ++k) {
        int v = (w >> (8 * k)) & 0xff;
        bool nz = (v != 0);
        p2 = nz ? p1 : p2;
        p1 = nz ? v  : p1;
        cnt += nz;
    }
}

// slow fallback: scan row bytes backward from element j0 (inclusive) for the
// last two nonzeros. row_chunk = first chunk slot of this row.
__device__ __noinline__ void peek_back(const unsigned char* s, int row_chunk,
                                       int j0, int& o1, int& o2)
{
    o1 = 127; o2 = 127;
    int found = 0;
    for (int j = j0; j >= 0 && found < 2; --j) {
        int v = s[(row_chunk + (j >> 6)) * CSTRIDE + (j & 63)];
        if (v) { if (!found) o1 = v; else o2 = v; ++found; }
    }
}

__global__ void __launch_bounds__(TPB, 5) pattern_kernel(
    const int4* __restrict__ x4, float4* __restrict__ out)
{
    __shared__ unsigned char s[TPB * CSTRIDE];   // 20480 B
    const int tid = threadIdx.x;

    // ---- Stage: coalesced gmem -> byte-packed smem ----
    const int4* src = x4 + (long long)blockIdx.x * (RPB * L_LEN / 4);
    #pragma unroll
    for (int it = 0; it < 16; ++it) {
        int idx = it * TPB + tid;
        int4 v  = src[idx];
        unsigned packed = (unsigned)v.x | ((unsigned)v.y << 8)
                        | ((unsigned)v.z << 16) | ((unsigned)v.w << 24);
        *(unsigned*)&s[(idx >> 4) * CSTRIDE + (idx & 15) * 4] = packed;
    }
    __syncthreads();

    const int c         = tid & 3;      // chunk within row
    const int row_chunk = tid & ~3;
    const int base      = c * 64;       // chunk's first element within row

    // ---- Load chunk ----
    const uint4* chunk = (const uint4*)&s[tid * CSTRIDE];
    uint4 q0 = chunk[0];
    uint4 q1 = chunk[1];
    uint4 q2 = chunk[2];
    uint4 q3 = chunk[3];

    // ---- Chain inits ----
    int p1c0 = 127, p2c0 = 127;            // C0: before element base
    if (c) {
        unsigned w = *(const unsigned*)&s[(tid - 1) * CSTRIDE + 60];
        int p1, p2, cnt;
        last2nz_word(w, p1, p2, cnt);
        if (cnt >= 2) { p1c0 = p1; p2c0 = p2; }
        else peek_back(s, row_chunk, base - 1, p1c0, p2c0);
    }
    int p1c1, p2c1, p1c2, p2c2, p1c3, p2c3;
    {
        int p1, p2, cnt;
        last2nz_word(q0.w, p1, p2, cnt);   // elements base+12..15
        if (cnt >= 2) { p1c1 = p1; p2c1 = p2; }
        else peek_back(s, row_chunk, base + 15, p1c1, p2c1);
        last2nz_word(q1.w, p1, p2, cnt);   // elements base+28..31
        if (cnt >= 2) { p1c2 = p1; p2c2 = p2; }
        else peek_back(s, row_chunk, base + 31, p1c2, p2c2);
        last2nz_word(q2.w, p1, p2, cnt);   // elements base+44..47
        if (cnt >= 2) { p1c3 = p1; p2c3 = p2; }
        else peek_back(s, row_chunk, base + 47, p1c3, p2c3);
    }

    // ---- Half2 state: X = {C0 low, C2 high}, Y = {C1 low, C3 high} ----
    const unsigned BIAS = 0x64006400u;    // half2 {1024, 1024}
    const unsigned BMSK = 0x00FF00FFu;
    __half2 p1X = h2bits((unsigned)(0x6400 | p1c0) | ((unsigned)(0x6400 | p1c2) << 16));
    __half2 p2X = h2bits((unsigned)(0x6400 | p2c0) | ((unsigned)(0x6400 | p2c2) << 16));
    __half2 p1Y = h2bits((unsigned)(0x6400 | p1c1) | ((unsigned)(0x6400 | p1c3) << 16));
    __half2 p2Y = h2bits((unsigned)(0x6400 | p2c1) | ((unsigned)(0x6400 | p2c3) << 16));
    __half2 zero1024 = h2bits(BIAS);
    __half2 accR = h2bits(0u), accI = h2bits(0u);
    __half2 accP = h2bits(0u), accN = h2bits(0u);

    // C0 words: q0.*, C1: q1.*, C2: q2.*, C3: q3.*
    unsigned W0[4] = {q0.x, q0.y, q0.z, q0.w};
    unsigned W1[4] = {q1.x, q1.y, q1.z, q1.w};
    unsigned W2[4] = {q2.x, q2.y, q2.z, q2.w};
    unsigned W3[4] = {q3.x, q3.y, q3.z, q3.w};

    #pragma unroll
    for (int w = 0; w < 4; ++w) {
        unsigned a0 = W0[w], a2 = W2[w];   // X chain sources
        unsigned a1 = W1[w], a3 = W3[w];   // Y chain sources
        #pragma unroll
        for (int k = 0; k < 4; ++k) {
            unsigned sel = 0x0400 + k * 0x0101;
            __half2 vX = h2bits((__byte_perm(a0, a2, sel) & BMSK) | BIAS);
            __half2 vY = h2bits((__byte_perm(a1, a3, sel) & BMSK) | BIAS);

            accR = __hadd2(accR, __heq2(vX, p1X));
            accI = __hadd2(accI, __hgt2(vX, p1X));
            accP = __hadd2(accP, __heq2(vX, p2X));
            __half2 nzX = __hne2(vX, zero1024);
            accN = __hadd2(accN, nzX);
            p2X = __hfma2(nzX, __hsub2(p1X, p2X), p2X);
            p1X = __hfma2(nzX, __hsub2(vX,  p1X), p1X);

            accR = __hadd2(accR, __heq2(vY, p1Y));
            accI = __hadd2(accI, __hgt2(vY, p1Y));
            accP = __hadd2(accP, __heq2(vY, p2Y));
            __half2 nzY = __hne2(vY, zero1024);
            accN = __hadd2(accN, nzY);
            p2Y = __hfma2(nzY, __hsub2(p1Y, p2Y), p2Y);
            p1Y = __hfma2(nzY, __hsub2(vY,  p1Y), p1Y);
        }
    }

    // ---- Reduce across the 4 chunk lanes (half2 adds exact, <=256) ----
    #pragma unroll
    for (int m = 1; m <= 2; m <<= 1) {
        accR = __hadd2(accR, h2bits(__shfl_xor_sync(0xffffffffu, bitsh2(accR), m)));
        accI = __hadd2(accI, h2bits(__shfl_xor_sync(0xffffffffu, bitsh2(accI), m)));
        accP = __hadd2(accP, h2bits(__shfl_xor_sync(0xffffffffu, bitsh2(accP), m)));
        accN = __hadd2(accN, h2bits(__shfl_xor_sync(0xffffffffu, bitsh2(accN), m)));
    }

    if (c == 0) {
        float REP = __half2float(__low2half(accR)) + __half2float(__high2half(accR));
        float INC = __half2float(__low2half(accI)) + __half2float(__high2half(accI));
        float PER = __half2float(__low2half(accP)) + __half2float(__high2half(accP));
        float NF  = __half2float(__low2half(accN)) + __half2float(__high2half(accN));
        int   N   = (int)NF;
        float o0 = 0.f, o1 = 0.f, o2 = 0.f, o3 = 0.f;
        if (N > 1) {
            float DEC = (NF - 1.0f) - REP - INC;
            float d1  = 1.0f / (NF - 1.0f);
            o0 = REP * d1;
            o1 = INC * d1;
            o2 = DEC * d1;
            if (N >= 4) o3 = PER / (NF - 2.0f);
        }
        out[(long long)blockIdx.x * RPB + (tid >> 2)] =
            make_float4(o0, o1, o2, o3);
    }
}

extern "C" void kernel_launch(void* const* d_in, const int* in_sizes, int n_in,
                              void* d_out, int out_size)
{
    const int4* x = (const int4*)d_in[0];
    float4* out   = (float4*)d_out;
    const int total_elems = in_sizes[0];      // B * L
    const int nrows  = total_elems / L_LEN;   // 131072
    const int blocks = nrows / RPB;           // 2048
    pattern_kernel<<<blocks, TPB>>>(x, out);
}